// round 8
// baseline (speedup 1.0000x reference)
#include <cuda_runtime.h>
#include <math.h>

#define BNS   8
#define CH    64
#define NPT   16384
#define KN    32
#define CN    256
#define CLEN  32
#define NCURVE 2048
#define NNODE  131072
#define WBLK  16
#define TPB   512
#define NBLK  128
#define EPSBN 1e-5f
#define DSMEM (WBLK*32*16*16) /* 131072 B staging */

__device__ float4 g_XW4[(size_t)NNODE * 16];   // gated features [node][64]
__device__ float  g_GATT[NNODE];               // dot(row, agent_w[0:64])
__device__ float  g_XATT[NNODE];               // sigmoid gate
__device__ int    g_START[NCURVE];
__device__ float  g_MMBUF[BNS * 2 * CN];       // raw momentum logits
__device__ float4 g_MMP4[NBLK];                // per-block momentum partials
__device__ float2 g_LGP2[NBLK];                // per-block logit partials
__device__ unsigned g_cnt0;
__device__ unsigned g_cnt1[8];
__device__ volatile unsigned g_genv;

__device__ __forceinline__ float wsum(float v) {
    #pragma unroll
    for (int o = 16; o; o >>= 1) v += __shfl_xor_sync(0xffffffffu, v, o);
    return v;
}
__device__ __forceinline__ double dsum32(double v) {
    #pragma unroll
    for (int o = 16; o; o >>= 1) v += __shfl_xor_sync(0xffffffffu, v, o);
    return v;
}
__device__ __forceinline__ void cpasync16(unsigned dst, const void* src) {
    asm volatile("cp.async.cg.shared.global [%0], [%1], 16;" :: "r"(dst), "l"(src));
}
// tree barrier: arrive (tid0 only inside) + per-warp wait
__device__ __forceinline__ void bar_arrive(unsigned myGen) {
    if (threadIdx.x == 0) {
        __threadfence();
        unsigned grp = blockIdx.x >> 4;
        if (atomicAdd(&g_cnt1[grp], 1u) == 15u) {
            atomicExch(&g_cnt1[grp], 0u);
            __threadfence();
            if (atomicAdd(&g_cnt0, 1u) == 7u) {
                atomicExch(&g_cnt0, 0u);
                __threadfence();
                g_genv = myGen;
            }
        }
    }
}
__device__ __forceinline__ void bar_wait(unsigned myGen, int lane) {
    if (lane == 0) { while (g_genv < myGen) __nanosleep(20); }
    __syncwarp();
    __threadfence();
}

// ---------------- K1: gate + gated table + per-node agent scalar ----------------
__global__ void __launch_bounds__(128) k_prep(const float* __restrict__ x,
                                              const float* __restrict__ att_w,
                                              const float* __restrict__ agent_w) {
    if (blockIdx.x == 0 && threadIdx.x == 0) {     // reset barrier state each launch
        g_genv = 0u; g_cnt0 = 0u;
        #pragma unroll
        for (int i = 0; i < 8; ++i) g_cnt1[i] = 0u;
    }
    int p = blockIdx.x * 128 + threadIdx.x;
    int b = p >> 14, n = p & (NPT - 1);
    const float* xb = x + (size_t)b * CH * NPT + n;
    float xv[CH], att = 0.f;
    #pragma unroll
    for (int c = 0; c < CH; ++c) {
        xv[c] = __ldg(xb + (size_t)c * NPT);
        att += xv[c] * __ldg(att_w + c);
    }
    float sg = 1.f / (1.f + expf(-att));
    g_XATT[p] = sg;
    float g = 0.f;
    #pragma unroll
    for (int t = 0; t < 16; ++t) {
        float4 v;
        v.x = xv[4*t+0]*sg; v.y = xv[4*t+1]*sg; v.z = xv[4*t+2]*sg; v.w = xv[4*t+3]*sg;
        g += v.x*__ldg(agent_w+4*t) + v.y*__ldg(agent_w+4*t+1)
           + v.z*__ldg(agent_w+4*t+2) + v.w*__ldg(agent_w+4*t+3);
        g_XW4[(size_t)p * 16 + t] = v;
    }
    g_GATT[p] = g;
}

// ---------------- K2: exact per-batch top-256 (value desc, index asc) ----------------
__global__ void __launch_bounds__(1024) k_topk() {
    const int b = blockIdx.x, tid = threadIdx.x;
    __shared__ unsigned hist[256];
    __shared__ unsigned sh_chosen, sh_rem, sh_cnt;
    __shared__ unsigned long long pool[1024];

    unsigned prefix = 0, rem = CN;
    for (int rb = 3; rb >= 0; --rb) {
        if (tid < 256) hist[tid] = 0u;
        __syncthreads();
        for (int i = tid; i < NPT; i += 1024) {
            unsigned key = __float_as_uint(g_XATT[b * NPT + i]);
            bool ok = (rb == 3) || ((key >> ((rb + 1) * 8)) == (prefix >> ((rb + 1) * 8)));
            if (ok) atomicAdd(&hist[(key >> (rb * 8)) & 255u], 1u);
        }
        __syncthreads();
        if (tid == 0) {
            unsigned cum = 0, chosen = 0;
            for (int dd = 255; dd >= 0; --dd) {
                unsigned c = hist[dd];
                if (cum + c >= rem) { chosen = (unsigned)dd; break; }
                cum += c;
            }
            sh_chosen = chosen; sh_rem = rem - cum;
        }
        __syncthreads();
        prefix |= (sh_chosen << (rb * 8));
        rem = sh_rem;
        __syncthreads();
    }
    if (tid == 0) sh_cnt = 0u;
    __syncthreads();
    for (int i = tid; i < NPT; i += 1024) {
        unsigned key = __float_as_uint(g_XATT[b * NPT + i]);
        if (key >= prefix) {
            unsigned p = atomicAdd(&sh_cnt, 1u);
            if (p < 1024u)
                pool[p] = (((unsigned long long)key) << 32) | (unsigned long long)(~(unsigned)i);
        }
    }
    __syncthreads();
    unsigned np = sh_cnt < 1024u ? sh_cnt : 1024u;
    if ((unsigned)tid >= np) pool[tid] = 0ull;
    __syncthreads();
    for (int k = 2; k <= 1024; k <<= 1)
        for (int j = k >> 1; j > 0; j >>= 1) {
            int ixj = tid ^ j;
            if (ixj > tid) {
                unsigned long long A = pool[tid], B = pool[ixj];
                bool sw = ((tid & k) == 0) ? (A < B) : (A > B);
                if (sw) { pool[tid] = B; pool[ixj] = A; }
            }
            __syncthreads();
        }
    if (tid < CN) {
        unsigned iv = ~(unsigned)(pool[tid] & 0xFFFFFFFFull);
        g_START[b * CN + tid] = b * NPT + (int)iv;
    }
}

// ---------------- K3: persistent walk, 1 warp = 1 curve ----------------
__global__ void __launch_bounds__(TPB, 1) k_walk(const int* __restrict__ idxp,
        const float* __restrict__ agent_wp, const float* __restrict__ agent_gp,
        const float* __restrict__ agent_bp, const float* __restrict__ mom_wp,
        const float* __restrict__ mom_gp, const float* __restrict__ mom_bp,
        float* __restrict__ out) {
    extern __shared__ float4 s_rows[];   // [WBLK][32 rows][16 float4], XOR-swizzled
    const int warp = threadIdx.x >> 5, lane = threadIdx.x & 31;
    const int m = blockIdx.x * WBLK + warp;
    const int b = m >> 8, ci = m & 255;
    const int bOff = b * NPT;
    const float* XWf = (const float*)g_XW4;
    const unsigned sbase = (unsigned)__cvta_generic_to_shared(s_rows);

    __shared__ float s_cur[WBLK][CH];
    __shared__ float s_a[WBLK][CH];
    __shared__ float s_red[WBLK][4];

    const int c1 = lane, c2 = lane + 32;
    const float aw1a = __ldg(agent_wp + 64 + c1), aw1b = __ldg(agent_wp + 64 + c2);
    const float ga = __ldg(agent_gp), ba = __ldg(agent_bp);
    const float gm0 = __ldg(mom_gp), gm1 = __ldg(mom_gp + 1);
    const float bm0 = __ldg(mom_bp), bm1 = __ldg(mom_bp + 1);
    const float mw0a = __ldg(mom_wp + c1),       mw0b = __ldg(mom_wp + c2);
    const float mw0c = __ldg(mom_wp + 64 + c1),  mw0d = __ldg(mom_wp + 64 + c2);
    const float mw1a = __ldg(mom_wp + 128 + c1), mw1b = __ldg(mom_wp + 128 + c2);
    const float mw1c = __ldg(mom_wp + 192 + c1), mw1d = __ldg(mom_wp + 192 + c2);

    int fcur = g_START[m];
    float rp1 = __ldg(XWf + (size_t)fcur * CH + c1);
    float rp2 = __ldg(XWf + (size_t)fcur * CH + c2);
    float rc1, rc2;
    const int j0 = lane * 4;
    unsigned bgen = 0;
    float lm, li;

    // ---------- step 0 ----------
    float h = wsum(rp1 * aw1a + rp2 * aw1b);
    int nbr = __ldg(idxp + (size_t)fcur * KN + lane) + bOff;
    float r = __ldg(g_GATT + nbr) + h;
    {
        float t0 = wsum(r), t1 = wsum(r * r);
        if (lane == 0) { s_red[warp][0] = t0; s_red[warp][1] = t1; }
    }
    __syncthreads();
    if (warp == 0 && lane < WBLK) {
        float v0 = s_red[lane][0], v1 = s_red[lane][1];
        #pragma unroll
        for (int o = 8; o; o >>= 1) {
            v0 += __shfl_xor_sync(0xffffu, v0, o);
            v1 += __shfl_xor_sync(0xffffu, v1, o);
        }
        if (lane == 0) g_LGP2[blockIdx.x] = make_float2(v0, v1);
    }
    ++bgen;
    bar_arrive(bgen);
    bar_wait(bgen, lane);
    {
        float2 p0 = __ldcg(&g_LGP2[j0]),     p1 = __ldcg(&g_LGP2[j0 + 1]);
        float2 p2 = __ldcg(&g_LGP2[j0 + 2]), p3 = __ldcg(&g_LGP2[j0 + 3]);
        double T0 = (double)p0.x + (double)p1.x + (double)p2.x + (double)p3.x;
        double T1 = (double)p0.y + (double)p1.y + (double)p2.y + (double)p3.y;
        T0 = dsum32(T0); T1 = dsum32(T1);
        double cnt = (double)NCURVE * KN, mu = T0 / cnt;
        lm = (float)mu;
        li = (float)(1.0 / sqrt(T1 / cnt - mu * mu + (double)EPSBN));
    }
    {
        float val = (r - lm) * li * ga + ba;
        float bv = val; int bk = lane;
        #pragma unroll
        for (int o = 16; o; o >>= 1) {
            float ov = __shfl_xor_sync(0xffffffffu, bv, o);
            int   ok = __shfl_xor_sync(0xffffffffu, bk, o);
            if (ov > bv || (ov == bv && ok < bk)) { bv = ov; bk = ok; }
        }
        int sel = __shfl_sync(0xffffffffu, nbr, bk);
        rc1 = __ldg(XWf + (size_t)sel * CH + c1);
        rc2 = __ldg(XWf + (size_t)sel * CH + c2);
        s_cur[warp][c1] = rc1; s_cur[warp][c2] = rc2;
        out[((size_t)(b * CH + c1) * CN + ci) * CLEN + 0] = rc1;
        out[((size_t)(b * CH + c2) * CN + ci) * CLEN + 0] = rc2;
        fcur = sel;
    }
    __syncwarp();

    // ---------- steps 1..31 ----------
    const int sh = lane >> 4, sc = lane & 15;
    for (int s = 1; s < CLEN; ++s) {
        // A: prefetch neighbors + stage rows (depends only on fcur)
        nbr = __ldg(idxp + (size_t)fcur * KN + lane) + bOff;
        float gatt = __ldg(g_GATT + nbr);
        #pragma unroll
        for (int t = 0; t < 16; ++t) {
            int rr = 2 * t + sh;
            int rn = __shfl_sync(0xffffffffu, nbr, rr);
            unsigned dst = sbase + ((unsigned)(warp * 512 + rr * 16 + (sc ^ (rr & 15))) << 4);
            cpasync16(dst, (const void*)(g_XW4 + (size_t)rn * 16 + sc));
        }
        asm volatile("cp.async.commit_group;");

        // B: momentum partials
        float mm0 = wsum(mw0a * rc1 + mw0b * rc2 + mw0c * rp1 + mw0d * rp2);
        float mm1 = wsum(mw1a * rc1 + mw1b * rc2 + mw1c * rp1 + mw1d * rp2);
        if (lane == 0) {
            g_MMBUF[b * 512 + ci]       = mm0;
            g_MMBUF[b * 512 + 256 + ci] = mm1;
            __threadfence();
            s_red[warp][0] = mm0; s_red[warp][1] = mm0 * mm0;
            s_red[warp][2] = mm1; s_red[warp][3] = mm1 * mm1;
        }
        __syncthreads();
        if (warp == 0 && lane < WBLK) {
            float v0 = s_red[lane][0], v1 = s_red[lane][1];
            float v2 = s_red[lane][2], v3 = s_red[lane][3];
            #pragma unroll
            for (int o = 8; o; o >>= 1) {
                v0 += __shfl_xor_sync(0xffffu, v0, o);
                v1 += __shfl_xor_sync(0xffffu, v1, o);
                v2 += __shfl_xor_sync(0xffffu, v2, o);
                v3 += __shfl_xor_sync(0xffffu, v3, o);
            }
            if (lane == 0) g_MMP4[blockIdx.x] = make_float4(v0, v1, v2, v3);
        }
        ++bgen;
        bar_arrive(bgen);
        bar_wait(bgen, lane);
        float mme0, mis0, mme1, mis1;
        {
            float4 p0 = __ldcg(&g_MMP4[j0]),     p1 = __ldcg(&g_MMP4[j0 + 1]);
            float4 p2 = __ldcg(&g_MMP4[j0 + 2]), p3 = __ldcg(&g_MMP4[j0 + 3]);
            double M0 = (double)p0.x + (double)p1.x + (double)p2.x + (double)p3.x;
            double M1 = (double)p0.y + (double)p1.y + (double)p2.y + (double)p3.y;
            double M2 = (double)p0.z + (double)p1.z + (double)p2.z + (double)p3.z;
            double M3 = (double)p0.w + (double)p1.w + (double)p2.w + (double)p3.w;
            M0 = dsum32(M0); M1 = dsum32(M1); M2 = dsum32(M2); M3 = dsum32(M3);
            double mu0 = M0 / 2048.0, mu1 = M2 / 2048.0;
            mme0 = (float)mu0;
            mis0 = (float)(1.0 / sqrt(M1 / 2048.0 - mu0 * mu0 + (double)EPSBN));
            mme1 = (float)mu1;
            mis1 = (float)(1.0 / sqrt(M3 / 2048.0 - mu1 * mu1 + (double)EPSBN));
        }

        // torch .view attention: curve ci reads softmaxed flat positions 2ci, 2ci+1
        float att0, att1;
        #pragma unroll
        for (int j = 0; j < 2; ++j) {
            int f = 2 * ci + j, o = f >> 8, n = f & 255;
            float z0 = (__ldcg(&g_MMBUF[b * 512 + n])       - mme0) * mis0 * gm0 + bm0;
            float z1 = (__ldcg(&g_MMBUF[b * 512 + 256 + n]) - mme1) * mis1 * gm1 + bm1;
            float mx = fmaxf(z0, z1);
            float e0 = expf(z0 - mx), e1 = expf(z1 - mx);
            float sm = ((o == 0) ? e0 : e1) / (e0 + e1);
            if (j == 0) att0 = sm; else att1 = sm;
        }
        float pn1 = rc1 * att0 + rp1 * att1;
        float pn2 = rc2 * att0 + rp2 * att1;
        float a1v = rc1 - pn1, a2v = rc2 - pn2;
        s_a[warp][c1] = a1v; s_a[warp][c2] = a2v;
        float anorm = sqrtf(wsum(a1v * a1v + a2v * a2v));
        float h2 = wsum(pn1 * aw1a + pn2 * aw1b);

        // C: agent logit partials (pre-suppression)
        r = gatt + h2;
        {
            float t0 = wsum(r), t1 = wsum(r * r);
            if (lane == 0) { s_red[warp][0] = t0; s_red[warp][1] = t1; }
        }
        __syncthreads();
        if (warp == 0 && lane < WBLK) {
            float v0 = s_red[lane][0], v1 = s_red[lane][1];
            #pragma unroll
            for (int o = 8; o; o >>= 1) {
                v0 += __shfl_xor_sync(0xffffu, v0, o);
                v1 += __shfl_xor_sync(0xffffu, v1, o);
            }
            if (lane == 0) g_LGP2[blockIdx.x] = make_float2(v0, v1);
        }
        ++bgen;
        bar_arrive(bgen);

        // D: crossover from staged smem (overlaps other blocks' arrivals)
        asm volatile("cp.async.wait_group 0;");
        __syncwarp();
        float dotv = 0.f, nrm = 0.f;
        {
            const int rbase = warp * 512 + lane * 16;
            const int jm = lane & 15;
            #pragma unroll
            for (int t = 0; t < 16; ++t) {
                float4 v = s_rows[rbase + (t ^ jm)];
                int cb = 4 * t; float df;
                df = v.x - s_cur[warp][cb];   dotv = fmaf(s_a[warp][cb],   df, dotv); nrm = fmaf(df, df, nrm);
                df = v.y - s_cur[warp][cb+1]; dotv = fmaf(s_a[warp][cb+1], df, dotv); nrm = fmaf(df, df, nrm);
                df = v.z - s_cur[warp][cb+2]; dotv = fmaf(s_a[warp][cb+2], df, dotv); nrm = fmaf(df, df, nrm);
                df = v.w - s_cur[warp][cb+3]; dotv = fmaf(s_a[warp][cb+3], df, dotv); nrm = fmaf(df, df, nrm);
            }
        }
        bar_wait(bgen, lane);
        {
            float2 p0 = __ldcg(&g_LGP2[j0]),     p1 = __ldcg(&g_LGP2[j0 + 1]);
            float2 p2 = __ldcg(&g_LGP2[j0 + 2]), p3 = __ldcg(&g_LGP2[j0 + 3]);
            double T0 = (double)p0.x + (double)p1.x + (double)p2.x + (double)p3.x;
            double T1 = (double)p0.y + (double)p1.y + (double)p2.y + (double)p3.y;
            T0 = dsum32(T0); T1 = dsum32(T1);
            double cnt = (double)NCURVE * KN, mu = T0 / cnt;
            lm = (float)mu;
            li = (float)(1.0 / sqrt(T1 / cnt - mu * mu + (double)EPSBN));
        }

        float val = (r - lm) * li * ga + ba;
        float div = fmaxf(anorm * sqrtf(nrm), 1e-8f);
        float dd = 1.f + dotv / div;
        dd = fminf(fmaxf(dd, 0.f), 1.f);
        val *= dd;

        float bv = val; int bk = lane;
        #pragma unroll
        for (int o = 16; o; o >>= 1) {
            float ov = __shfl_xor_sync(0xffffffffu, bv, o);
            int   ok = __shfl_xor_sync(0xffffffffu, bk, o);
            if (ov > bv || (ov == bv && ok < bk)) { bv = ov; bk = ok; }
        }
        int sel = __shfl_sync(0xffffffffu, nbr, bk);
        rp1 = pn1; rp2 = pn2;
        // cur row from staged smem (row bk): channel c -> chunk c>>2, comp c&3
        {
            const int rb2 = warp * 512 + bk * 16, km = bk & 15;
            float4 v1 = s_rows[rb2 + ((lane >> 2) ^ km)];
            float4 v2 = s_rows[rb2 + (((lane >> 2) + 8) ^ km)];
            int cc = lane & 3;
            rc1 = (cc == 0) ? v1.x : (cc == 1) ? v1.y : (cc == 2) ? v1.z : v1.w;
            rc2 = (cc == 0) ? v2.x : (cc == 1) ? v2.y : (cc == 2) ? v2.z : v2.w;
        }
        s_cur[warp][c1] = rc1; s_cur[warp][c2] = rc2;
        out[((size_t)(b * CH + c1) * CN + ci) * CLEN + s] = rc1;
        out[((size_t)(b * CH + c2) * CN + ci) * CLEN + s] = rc2;
        fcur = sel;
        __syncwarp();
    }
}

extern "C" void kernel_launch(void* const* d_in, const int* in_sizes, int n_in,
                              void* d_out, int out_size) {
    const float* x       = (const float*)d_in[0];
    const int*   idx     = (const int*)d_in[2];
    const float* att_w   = (const float*)d_in[3];
    const float* agent_w = (const float*)d_in[4];
    const float* agent_g = (const float*)d_in[5];
    const float* agent_b = (const float*)d_in[6];
    const float* mom_w   = (const float*)d_in[7];
    const float* mom_g   = (const float*)d_in[8];
    const float* mom_b   = (const float*)d_in[9];
    float* out = (float*)d_out;
    (void)in_sizes; (void)n_in; (void)out_size;

    cudaFuncSetAttribute(k_walk, cudaFuncAttributeMaxDynamicSharedMemorySize, DSMEM);

    k_prep<<<NNODE / 128, 128>>>(x, att_w, agent_w);
    k_topk<<<BNS, 1024>>>();
    k_walk<<<NBLK, TPB, DSMEM>>>(idx, agent_w, agent_g, agent_b, mom_w, mom_g, mom_b, out);
}

// round 9
// speedup vs baseline: 1.2886x; 1.2886x over previous
#include <cuda_runtime.h>
#include <math.h>

#define BNS   8
#define CH    64
#define NPT   16384
#define KN    32
#define CN    256
#define CLEN  32
#define NCURVE 2048
#define NNODE  131072
#define WBLK  16
#define TPB   512
#define NBLK  128
#define EPSBN 1e-5f
#define DSMEM (WBLK*32*16*16) /* 131072 B staging */

__device__ float4 g_XW4[(size_t)NNODE * 16];   // gated features [node][64]
__device__ float  g_GATT[NNODE];               // dot(row, agent_w[0:64])
__device__ float  g_XATT[NNODE];               // sigmoid gate
__device__ int    g_START[NCURVE];
__device__ float  g_MMBUF[BNS * 2 * CN];       // raw momentum logits
__device__ float4 g_MMP4[NBLK];                // per-block momentum partials
__device__ float2 g_LGP2[NBLK];                // per-block logit partials
__device__ unsigned g_barcnt;
__device__ volatile unsigned g_bargen;

__device__ __forceinline__ void gridbar() {
    __syncthreads();
    if (threadIdx.x == 0) {
        unsigned gen = g_bargen;
        __threadfence();
        if (atomicAdd(&g_barcnt, 1u) == (unsigned)(NBLK - 1)) {
            atomicExch(&g_barcnt, 0u);
            __threadfence();
            g_bargen = gen + 1u;
        } else {
            while (g_bargen == gen) {}   // tight spin: 1 thread/block only
        }
        __threadfence();
    }
    __syncthreads();
}

__device__ __forceinline__ float wsum(float v) {
    #pragma unroll
    for (int o = 16; o; o >>= 1) v += __shfl_xor_sync(0xffffffffu, v, o);
    return v;
}
__device__ __forceinline__ double dsum32(double v) {
    #pragma unroll
    for (int o = 16; o; o >>= 1) v += __shfl_xor_sync(0xffffffffu, v, o);
    return v;
}
__device__ __forceinline__ void cpasync16(unsigned dst, const void* src) {
    asm volatile("cp.async.cg.shared.global [%0], [%1], 16;" :: "r"(dst), "l"(src));
}

// ---------------- K1: gate + gated table + per-node agent scalar ----------------
__global__ void __launch_bounds__(128) k_prep(const float* __restrict__ x,
                                              const float* __restrict__ att_w,
                                              const float* __restrict__ agent_w) {
    int p = blockIdx.x * 128 + threadIdx.x;
    int b = p >> 14, n = p & (NPT - 1);
    const float* xb = x + (size_t)b * CH * NPT + n;
    float xv[CH], att = 0.f;
    #pragma unroll
    for (int c = 0; c < CH; ++c) {
        xv[c] = __ldg(xb + (size_t)c * NPT);
        att += xv[c] * __ldg(att_w + c);
    }
    float sg = 1.f / (1.f + expf(-att));
    g_XATT[p] = sg;
    float g = 0.f;
    #pragma unroll
    for (int t = 0; t < 16; ++t) {
        float4 v;
        v.x = xv[4*t+0]*sg; v.y = xv[4*t+1]*sg; v.z = xv[4*t+2]*sg; v.w = xv[4*t+3]*sg;
        g += v.x*__ldg(agent_w+4*t) + v.y*__ldg(agent_w+4*t+1)
           + v.z*__ldg(agent_w+4*t+2) + v.w*__ldg(agent_w+4*t+3);
        g_XW4[(size_t)p * 16 + t] = v;
    }
    g_GATT[p] = g;
}

// ---------------- K2: exact per-batch top-256 (value desc, index asc) ----------------
__global__ void __launch_bounds__(1024) k_topk() {
    const int b = blockIdx.x, tid = threadIdx.x;
    __shared__ unsigned hist[256];
    __shared__ unsigned sh_chosen, sh_rem, sh_cnt;
    __shared__ unsigned long long pool[1024];

    unsigned prefix = 0, rem = CN;
    for (int rb = 3; rb >= 0; --rb) {
        if (tid < 256) hist[tid] = 0u;
        __syncthreads();
        for (int i = tid; i < NPT; i += 1024) {
            unsigned key = __float_as_uint(g_XATT[b * NPT + i]);
            bool ok = (rb == 3) || ((key >> ((rb + 1) * 8)) == (prefix >> ((rb + 1) * 8)));
            if (ok) atomicAdd(&hist[(key >> (rb * 8)) & 255u], 1u);
        }
        __syncthreads();
        if (tid == 0) {
            unsigned cum = 0, chosen = 0;
            for (int dd = 255; dd >= 0; --dd) {
                unsigned c = hist[dd];
                if (cum + c >= rem) { chosen = (unsigned)dd; break; }
                cum += c;
            }
            sh_chosen = chosen; sh_rem = rem - cum;
        }
        __syncthreads();
        prefix |= (sh_chosen << (rb * 8));
        rem = sh_rem;
        __syncthreads();
    }
    if (tid == 0) sh_cnt = 0u;
    __syncthreads();
    for (int i = tid; i < NPT; i += 1024) {
        unsigned key = __float_as_uint(g_XATT[b * NPT + i]);
        if (key >= prefix) {
            unsigned p = atomicAdd(&sh_cnt, 1u);
            if (p < 1024u)
                pool[p] = (((unsigned long long)key) << 32) | (unsigned long long)(~(unsigned)i);
        }
    }
    __syncthreads();
    unsigned np = sh_cnt < 1024u ? sh_cnt : 1024u;
    if ((unsigned)tid >= np) pool[tid] = 0ull;
    __syncthreads();
    for (int k = 2; k <= 1024; k <<= 1)
        for (int j = k >> 1; j > 0; j >>= 1) {
            int ixj = tid ^ j;
            if (ixj > tid) {
                unsigned long long A = pool[tid], B = pool[ixj];
                bool sw = ((tid & k) == 0) ? (A < B) : (A > B);
                if (sw) { pool[tid] = B; pool[ixj] = A; }
            }
            __syncthreads();
        }
    if (tid < CN) {
        unsigned iv = ~(unsigned)(pool[tid] & 0xFFFFFFFFull);
        g_START[b * CN + tid] = b * NPT + (int)iv;
    }
}

// ---------------- K3: persistent walk, 1 warp = 1 curve ----------------
__global__ void __launch_bounds__(TPB, 1) k_walk(const int* __restrict__ idxp,
        const float* __restrict__ agent_wp, const float* __restrict__ agent_gp,
        const float* __restrict__ agent_bp, const float* __restrict__ mom_wp,
        const float* __restrict__ mom_gp, const float* __restrict__ mom_bp,
        float* __restrict__ out) {
    extern __shared__ float4 s_rows[];   // [WBLK][32 rows][16 float4], XOR-swizzled
    const int warp = threadIdx.x >> 5, lane = threadIdx.x & 31;
    const int m = blockIdx.x * WBLK + warp;
    const int b = m >> 8, ci = m & 255;
    const int bOff = b * NPT;
    const float* XWf = (const float*)g_XW4;
    const unsigned sbase = (unsigned)__cvta_generic_to_shared(s_rows);

    __shared__ float s_cur[WBLK][CH];
    __shared__ float s_a[WBLK][CH];
    __shared__ float s_red[WBLK][4];

    const int c1 = lane, c2 = lane + 32;
    const float aw1a = __ldg(agent_wp + 64 + c1), aw1b = __ldg(agent_wp + 64 + c2);
    const float ga = __ldg(agent_gp), ba = __ldg(agent_bp);
    const float gm0 = __ldg(mom_gp), gm1 = __ldg(mom_gp + 1);
    const float bm0 = __ldg(mom_bp), bm1 = __ldg(mom_bp + 1);
    const float mw0a = __ldg(mom_wp + c1),       mw0b = __ldg(mom_wp + c2);
    const float mw0c = __ldg(mom_wp + 64 + c1),  mw0d = __ldg(mom_wp + 64 + c2);
    const float mw1a = __ldg(mom_wp + 128 + c1), mw1b = __ldg(mom_wp + 128 + c2);
    const float mw1c = __ldg(mom_wp + 192 + c1), mw1d = __ldg(mom_wp + 192 + c2);

    int fcur = g_START[m];
    float rp1 = __ldg(XWf + (size_t)fcur * CH + c1);
    float rp2 = __ldg(XWf + (size_t)fcur * CH + c2);
    float rc1, rc2;
    const int j0 = lane * 4;
    float lm, li;

    // ---------- step 0 ----------
    float h = wsum(rp1 * aw1a + rp2 * aw1b);
    int nbr = __ldg(idxp + (size_t)fcur * KN + lane) + bOff;
    float r = __ldg(g_GATT + nbr) + h;
    {
        float t0 = wsum(r), t1 = wsum(r * r);
        if (lane == 0) { s_red[warp][0] = t0; s_red[warp][1] = t1; }
    }
    __syncthreads();
    if (warp == 0 && lane < WBLK) {
        float v0 = s_red[lane][0], v1 = s_red[lane][1];
        #pragma unroll
        for (int o = 8; o; o >>= 1) {
            v0 += __shfl_xor_sync(0xffffu, v0, o);
            v1 += __shfl_xor_sync(0xffffu, v1, o);
        }
        if (lane == 0) { g_LGP2[blockIdx.x] = make_float2(v0, v1); }
    }
    gridbar();
    {
        float2 p0 = __ldcg(&g_LGP2[j0]),     p1 = __ldcg(&g_LGP2[j0 + 1]);
        float2 p2 = __ldcg(&g_LGP2[j0 + 2]), p3 = __ldcg(&g_LGP2[j0 + 3]);
        double T0 = (double)p0.x + (double)p1.x + (double)p2.x + (double)p3.x;
        double T1 = (double)p0.y + (double)p1.y + (double)p2.y + (double)p3.y;
        T0 = dsum32(T0); T1 = dsum32(T1);
        double cnt = (double)NCURVE * KN, mu = T0 / cnt;
        lm = (float)mu;
        li = (float)(1.0 / sqrt(T1 / cnt - mu * mu + (double)EPSBN));
    }
    {
        float val = (r - lm) * li * ga + ba;
        float bv = val; int bk = lane;
        #pragma unroll
        for (int o = 16; o; o >>= 1) {
            float ov = __shfl_xor_sync(0xffffffffu, bv, o);
            int   ok = __shfl_xor_sync(0xffffffffu, bk, o);
            if (ov > bv || (ov == bv && ok < bk)) { bv = ov; bk = ok; }
        }
        int sel = __shfl_sync(0xffffffffu, nbr, bk);
        rc1 = __ldg(XWf + (size_t)sel * CH + c1);
        rc2 = __ldg(XWf + (size_t)sel * CH + c2);
        s_cur[warp][c1] = rc1; s_cur[warp][c2] = rc2;
        out[((size_t)(b * CH + c1) * CN + ci) * CLEN + 0] = rc1;
        out[((size_t)(b * CH + c2) * CN + ci) * CLEN + 0] = rc2;
        fcur = sel;
    }
    __syncwarp();

    // ---------- steps 1..31 ----------
    const int sh = lane >> 4, sc = lane & 15;
    for (int s = 1; s < CLEN; ++s) {
        // A: prefetch neighbors + stage rows (depends only on fcur)
        nbr = __ldg(idxp + (size_t)fcur * KN + lane) + bOff;
        float gatt = __ldg(g_GATT + nbr);
        #pragma unroll
        for (int t = 0; t < 16; ++t) {
            int rr = 2 * t + sh;
            int rn = __shfl_sync(0xffffffffu, nbr, rr);
            unsigned dst = sbase + ((unsigned)(warp * 512 + rr * 16 + (sc ^ (rr & 15))) << 4);
            cpasync16(dst, (const void*)(g_XW4 + (size_t)rn * 16 + sc));
        }
        asm volatile("cp.async.commit_group;");

        // B: momentum partials
        float mm0 = wsum(mw0a * rc1 + mw0b * rc2 + mw0c * rp1 + mw0d * rp2);
        float mm1 = wsum(mw1a * rc1 + mw1b * rc2 + mw1c * rp1 + mw1d * rp2);
        if (lane == 0) {
            g_MMBUF[b * 512 + ci]       = mm0;
            g_MMBUF[b * 512 + 256 + ci] = mm1;
            s_red[warp][0] = mm0; s_red[warp][1] = mm0 * mm0;
            s_red[warp][2] = mm1; s_red[warp][3] = mm1 * mm1;
        }
        __syncthreads();
        if (warp == 0 && lane < WBLK) {
            float v0 = s_red[lane][0], v1 = s_red[lane][1];
            float v2 = s_red[lane][2], v3 = s_red[lane][3];
            #pragma unroll
            for (int o = 8; o; o >>= 1) {
                v0 += __shfl_xor_sync(0xffffu, v0, o);
                v1 += __shfl_xor_sync(0xffffu, v1, o);
                v2 += __shfl_xor_sync(0xffffu, v2, o);
                v3 += __shfl_xor_sync(0xffffu, v3, o);
            }
            if (lane == 0) { g_MMP4[blockIdx.x] = make_float4(v0, v1, v2, v3); }
        }
        gridbar();
        float mme0, mis0, mme1, mis1;
        {
            float4 p0 = __ldcg(&g_MMP4[j0]),     p1 = __ldcg(&g_MMP4[j0 + 1]);
            float4 p2 = __ldcg(&g_MMP4[j0 + 2]), p3 = __ldcg(&g_MMP4[j0 + 3]);
            double M0 = (double)p0.x + (double)p1.x + (double)p2.x + (double)p3.x;
            double M1 = (double)p0.y + (double)p1.y + (double)p2.y + (double)p3.y;
            double M2 = (double)p0.z + (double)p1.z + (double)p2.z + (double)p3.z;
            double M3 = (double)p0.w + (double)p1.w + (double)p2.w + (double)p3.w;
            M0 = dsum32(M0); M1 = dsum32(M1); M2 = dsum32(M2); M3 = dsum32(M3);
            double mu0 = M0 / 2048.0, mu1 = M2 / 2048.0;
            mme0 = (float)mu0;
            mis0 = (float)(1.0 / sqrt(M1 / 2048.0 - mu0 * mu0 + (double)EPSBN));
            mme1 = (float)mu1;
            mis1 = (float)(1.0 / sqrt(M3 / 2048.0 - mu1 * mu1 + (double)EPSBN));
        }

        // torch .view attention: curve ci reads softmaxed flat positions 2ci, 2ci+1
        float att0, att1;
        #pragma unroll
        for (int j = 0; j < 2; ++j) {
            int f = 2 * ci + j, o = f >> 8, n = f & 255;
            float z0 = (__ldcg(&g_MMBUF[b * 512 + n])       - mme0) * mis0 * gm0 + bm0;
            float z1 = (__ldcg(&g_MMBUF[b * 512 + 256 + n]) - mme1) * mis1 * gm1 + bm1;
            float mx = fmaxf(z0, z1);
            float e0 = expf(z0 - mx), e1 = expf(z1 - mx);
            float sm = ((o == 0) ? e0 : e1) / (e0 + e1);
            if (j == 0) att0 = sm; else att1 = sm;
        }
        float pn1 = rc1 * att0 + rp1 * att1;
        float pn2 = rc2 * att0 + rp2 * att1;
        float a1v = rc1 - pn1, a2v = rc2 - pn2;
        s_a[warp][c1] = a1v; s_a[warp][c2] = a2v;
        float anorm = sqrtf(wsum(a1v * a1v + a2v * a2v));
        float h2 = wsum(pn1 * aw1a + pn2 * aw1b);

        // C: agent logit partials (pre-suppression)
        r = gatt + h2;
        {
            float t0 = wsum(r), t1 = wsum(r * r);
            if (lane == 0) { s_red[warp][0] = t0; s_red[warp][1] = t1; }
        }
        __syncthreads();
        if (warp == 0 && lane < WBLK) {
            float v0 = s_red[lane][0], v1 = s_red[lane][1];
            #pragma unroll
            for (int o = 8; o; o >>= 1) {
                v0 += __shfl_xor_sync(0xffffu, v0, o);
                v1 += __shfl_xor_sync(0xffffu, v1, o);
            }
            if (lane == 0) { g_LGP2[blockIdx.x] = make_float2(v0, v1); }
        }

        // D: crossover from staged smem (before the barrier, overlapping skew)
        asm volatile("cp.async.wait_group 0;");
        __syncwarp();
        float dotv = 0.f, nrm = 0.f;
        {
            const int rbase = warp * 512 + lane * 16;
            const int jm = lane & 15;
            #pragma unroll
            for (int t = 0; t < 16; ++t) {
                float4 v = s_rows[rbase + (t ^ jm)];
                int cb = 4 * t; float df;
                df = v.x - s_cur[warp][cb];   dotv = fmaf(s_a[warp][cb],   df, dotv); nrm = fmaf(df, df, nrm);
                df = v.y - s_cur[warp][cb+1]; dotv = fmaf(s_a[warp][cb+1], df, dotv); nrm = fmaf(df, df, nrm);
                df = v.z - s_cur[warp][cb+2]; dotv = fmaf(s_a[warp][cb+2], df, dotv); nrm = fmaf(df, df, nrm);
                df = v.w - s_cur[warp][cb+3]; dotv = fmaf(s_a[warp][cb+3], df, dotv); nrm = fmaf(df, df, nrm);
            }
        }
        gridbar();
        {
            float2 p0 = __ldcg(&g_LGP2[j0]),     p1 = __ldcg(&g_LGP2[j0 + 1]);
            float2 p2 = __ldcg(&g_LGP2[j0 + 2]), p3 = __ldcg(&g_LGP2[j0 + 3]);
            double T0 = (double)p0.x + (double)p1.x + (double)p2.x + (double)p3.x;
            double T1 = (double)p0.y + (double)p1.y + (double)p2.y + (double)p3.y;
            T0 = dsum32(T0); T1 = dsum32(T1);
            double cnt = (double)NCURVE * KN, mu = T0 / cnt;
            lm = (float)mu;
            li = (float)(1.0 / sqrt(T1 / cnt - mu * mu + (double)EPSBN));
        }

        float val = (r - lm) * li * ga + ba;
        float div = fmaxf(anorm * sqrtf(nrm), 1e-8f);
        float dd = 1.f + dotv / div;
        dd = fminf(fmaxf(dd, 0.f), 1.f);
        val *= dd;

        float bv = val; int bk = lane;
        #pragma unroll
        for (int o = 16; o; o >>= 1) {
            float ov = __shfl_xor_sync(0xffffffffu, bv, o);
            int   ok = __shfl_xor_sync(0xffffffffu, bk, o);
            if (ov > bv || (ov == bv && ok < bk)) { bv = ov; bk = ok; }
        }
        int sel = __shfl_sync(0xffffffffu, nbr, bk);
        rp1 = pn1; rp2 = pn2;
        // cur row from staged smem (verified correct in R8)
        {
            const int rb2 = warp * 512 + bk * 16, km = bk & 15;
            float4 v1 = s_rows[rb2 + ((lane >> 2) ^ km)];
            float4 v2 = s_rows[rb2 + (((lane >> 2) + 8) ^ km)];
            int cc = lane & 3;
            rc1 = (cc == 0) ? v1.x : (cc == 1) ? v1.y : (cc == 2) ? v1.z : v1.w;
            rc2 = (cc == 0) ? v2.x : (cc == 1) ? v2.y : (cc == 2) ? v2.z : v2.w;
        }
        s_cur[warp][c1] = rc1; s_cur[warp][c2] = rc2;
        out[((size_t)(b * CH + c1) * CN + ci) * CLEN + s] = rc1;
        out[((size_t)(b * CH + c2) * CN + ci) * CLEN + s] = rc2;
        fcur = sel;
        __syncwarp();
    }
}

extern "C" void kernel_launch(void* const* d_in, const int* in_sizes, int n_in,
                              void* d_out, int out_size) {
    const float* x       = (const float*)d_in[0];
    const int*   idx     = (const int*)d_in[2];
    const float* att_w   = (const float*)d_in[3];
    const float* agent_w = (const float*)d_in[4];
    const float* agent_g = (const float*)d_in[5];
    const float* agent_b = (const float*)d_in[6];
    const float* mom_w   = (const float*)d_in[7];
    const float* mom_g   = (const float*)d_in[8];
    const float* mom_b   = (const float*)d_in[9];
    float* out = (float*)d_out;
    (void)in_sizes; (void)n_in; (void)out_size;

    cudaFuncSetAttribute(k_walk, cudaFuncAttributeMaxDynamicSharedMemorySize, DSMEM);

    k_prep<<<NNODE / 128, 128>>>(x, att_w, agent_w);
    k_topk<<<BNS, 1024>>>();
    k_walk<<<NBLK, TPB, DSMEM>>>(idx, agent_w, agent_g, agent_b, mom_w, mom_g, mom_b, out);
}

// round 11
// speedup vs baseline: 4.0125x; 3.1137x over previous
#include <cuda_runtime.h>
#include <math.h>

#define BNS   8
#define CH    64
#define NPT   16384
#define KN    32
#define CN    256
#define CLEN  32
#define NCURVE 2048
#define NNODE  131072
#define WBLK  16
#define TPB   544            /* 16 curve warps + 1 handler warp */
#define NBLK  128
#define EPSBN 1e-5f
#define DSMEM (WBLK*32*16*16) /* 131072 B staging */

__device__ float4 g_XW4[(size_t)NNODE * 16];   // gated features [node][64]
__device__ float  g_GATT[NNODE];               // dot(row, agent_w[0:64])
__device__ float  g_XATT[NNODE];               // sigmoid gate
__device__ int    g_START[NCURVE];
__device__ float  g_MMBUF[BNS * 2 * CN];       // raw momentum logits
__device__ float4 g_MMP4[NBLK];                // per-block momentum partials
__device__ float2 g_LGP2[NBLK];                // per-block logit partials
__device__ unsigned g_c0, g_c1[8];             // tree-barrier counters
__device__ unsigned g_flagM[8 * 32];           // per-group release lines (128B apart)
__device__ unsigned g_flagL[8 * 32];

__device__ __forceinline__ float wsum(float v) {
    #pragma unroll
    for (int o = 16; o; o >>= 1) v += __shfl_xor_sync(0xffffffffu, v, o);
    return v;
}
__device__ __forceinline__ double dsum32(double v) {
    #pragma unroll
    for (int o = 16; o; o >>= 1) v += __shfl_xor_sync(0xffffffffu, v, o);
    return v;
}
__device__ __forceinline__ void cpasync16(unsigned dst, const void* src) {
    asm volatile("cp.async.cg.shared.global [%0], [%1], 16;" :: "r"(dst), "l"(src));
}
__device__ __forceinline__ unsigned ldflag(const unsigned* p) {
    unsigned v;
    asm volatile("ld.global.cg.u32 %0, [%1];" : "=r"(v) : "l"(p) : "memory");
    return v;
}
__device__ __forceinline__ void stflag(unsigned* p, unsigned v) {
    asm volatile("st.global.cg.u32 [%0], %1;" :: "l"(p), "r"(v) : "memory");
}

// ---------------- K1: gate + gated table + per-node agent scalar ----------------
__global__ void __launch_bounds__(128) k_prep(const float* __restrict__ x,
                                              const float* __restrict__ att_w,
                                              const float* __restrict__ agent_w) {
    if (blockIdx.x == 0 && threadIdx.x == 0) {     // reset barrier state each launch
        g_c0 = 0u;
        #pragma unroll
        for (int i = 0; i < 8; ++i) {
            g_c1[i] = 0u; g_flagM[i * 32] = 0u; g_flagL[i * 32] = 0u;
        }
    }
    int p = blockIdx.x * 128 + threadIdx.x;
    int b = p >> 14, n = p & (NPT - 1);
    const float* xb = x + (size_t)b * CH * NPT + n;
    float xv[CH], att = 0.f;
    #pragma unroll
    for (int c = 0; c < CH; ++c) {
        xv[c] = __ldg(xb + (size_t)c * NPT);
        att += xv[c] * __ldg(att_w + c);
    }
    float sg = 1.f / (1.f + expf(-att));
    g_XATT[p] = sg;
    float g = 0.f;
    #pragma unroll
    for (int t = 0; t < 16; ++t) {
        float4 v;
        v.x = xv[4*t+0]*sg; v.y = xv[4*t+1]*sg; v.z = xv[4*t+2]*sg; v.w = xv[4*t+3]*sg;
        g += v.x*__ldg(agent_w+4*t) + v.y*__ldg(agent_w+4*t+1)
           + v.z*__ldg(agent_w+4*t+2) + v.w*__ldg(agent_w+4*t+3);
        g_XW4[(size_t)p * 16 + t] = v;
    }
    g_GATT[p] = g;
}

// ---------------- K2: exact per-batch top-256 (value desc, index asc) ----------------
__global__ void __launch_bounds__(1024) k_topk() {
    const int b = blockIdx.x, tid = threadIdx.x;
    __shared__ unsigned hist[256];
    __shared__ unsigned sh_chosen, sh_rem, sh_cnt;
    __shared__ unsigned long long pool[1024];

    unsigned prefix = 0, rem = CN;
    for (int rb = 3; rb >= 0; --rb) {
        if (tid < 256) hist[tid] = 0u;
        __syncthreads();
        for (int i = tid; i < NPT; i += 1024) {
            unsigned key = __float_as_uint(g_XATT[b * NPT + i]);
            bool ok = (rb == 3) || ((key >> ((rb + 1) * 8)) == (prefix >> ((rb + 1) * 8)));
            if (ok) atomicAdd(&hist[(key >> (rb * 8)) & 255u], 1u);
        }
        __syncthreads();
        if (tid == 0) {
            unsigned cum = 0, chosen = 0;
            for (int dd = 255; dd >= 0; --dd) {
                unsigned c = hist[dd];
                if (cum + c >= rem) { chosen = (unsigned)dd; break; }
                cum += c;
            }
            sh_chosen = chosen; sh_rem = rem - cum;
        }
        __syncthreads();
        prefix |= (sh_chosen << (rb * 8));
        rem = sh_rem;
        __syncthreads();
    }
    if (tid == 0) sh_cnt = 0u;
    __syncthreads();
    for (int i = tid; i < NPT; i += 1024) {
        unsigned key = __float_as_uint(g_XATT[b * NPT + i]);
        if (key >= prefix) {
            unsigned p = atomicAdd(&sh_cnt, 1u);
            if (p < 1024u)
                pool[p] = (((unsigned long long)key) << 32) | (unsigned long long)(~(unsigned)i);
        }
    }
    __syncthreads();
    unsigned np = sh_cnt < 1024u ? sh_cnt : 1024u;
    if ((unsigned)tid >= np) pool[tid] = 0ull;
    __syncthreads();
    for (int k = 2; k <= 1024; k <<= 1)
        for (int j = k >> 1; j > 0; j >>= 1) {
            int ixj = tid ^ j;
            if (ixj > tid) {
                unsigned long long A = pool[tid], B = pool[ixj];
                bool sw = ((tid & k) == 0) ? (A < B) : (A > B);
                if (sw) { pool[tid] = B; pool[ixj] = A; }
            }
            __syncthreads();
        }
    if (tid < CN) {
        unsigned iv = ~(unsigned)(pool[tid] & 0xFFFFFFFFull);
        g_START[b * CN + tid] = b * NPT + (int)iv;
    }
}

// ---------------- K3: persistent walk, 1 warp = 1 curve + 1 handler warp ----------------
__global__ void __launch_bounds__(TPB, 1) k_walk(const int* __restrict__ idxp,
        const float* __restrict__ agent_wp, const float* __restrict__ agent_gp,
        const float* __restrict__ agent_bp, const float* __restrict__ mom_wp,
        const float* __restrict__ mom_gp, const float* __restrict__ mom_bp,
        float* __restrict__ out) {
    extern __shared__ float4 s_rows[];   // [WBLK][32 rows][16 float4], XOR-swizzled
    const int warp = threadIdx.x >> 5, lane = threadIdx.x & 31;
    const bool isH = (warp == WBLK);                 // handler warp
    const int m = blockIdx.x * WBLK + (isH ? 0 : warp);
    const int b = m >> 8, ci = m & 255;
    const int bOff = b * NPT;
    const float* XWf = (const float*)g_XW4;
    const unsigned sbase = (unsigned)__cvta_generic_to_shared(s_rows);
    const unsigned grp = blockIdx.x >> 4;

    __shared__ float s_cur[WBLK][CH];
    __shared__ float s_a[WBLK][CH];
    __shared__ float s_red[WBLK][4];
    __shared__ float s_st[8];

    const int c1 = lane, c2 = lane + 32;
    const float aw1a = __ldg(agent_wp + 64 + c1), aw1b = __ldg(agent_wp + 64 + c2);
    const float ga = __ldg(agent_gp), ba = __ldg(agent_bp);
    const float gm0 = __ldg(mom_gp), gm1 = __ldg(mom_gp + 1);
    const float bm0 = __ldg(mom_bp), bm1 = __ldg(mom_bp + 1);
    const float mw0a = __ldg(mom_wp + c1),       mw0b = __ldg(mom_wp + c2);
    const float mw0c = __ldg(mom_wp + 64 + c1),  mw0d = __ldg(mom_wp + 64 + c2);
    const float mw1a = __ldg(mom_wp + 128 + c1), mw1b = __ldg(mom_wp + 128 + c2);
    const float mw1c = __ldg(mom_wp + 192 + c1), mw1d = __ldg(mom_wp + 192 + c2);

    int fcur = isH ? 0 : g_START[m];
    float rp1 = __ldg(XWf + (size_t)fcur * CH + c1);
    float rp2 = __ldg(XWf + (size_t)fcur * CH + c2);
    float rc1 = 0.f, rc2 = 0.f;
    const int j0 = lane * 4;
    int nbr = 0; float r = 0.f, gatt = 0.f;

    // ---------- step 0: logits only ----------
    if (!isH) {
        float h = wsum(rp1 * aw1a + rp2 * aw1b);
        nbr = __ldg(idxp + (size_t)fcur * KN + lane) + bOff;
        r = __ldg(g_GATT + nbr) + h;
        float t0 = wsum(r), t1 = wsum(r * r);
        if (lane == 0) { s_red[warp][0] = t0; s_red[warp][1] = t1; }
    }
    __syncthreads();
    if (isH) {
        float v0 = 0.f, v1 = 0.f;
        if (lane < WBLK) {
            v0 = s_red[lane][0]; v1 = s_red[lane][1];
            #pragma unroll
            for (int o = 8; o; o >>= 1) {
                v0 += __shfl_xor_sync(0xffffu, v0, o);
                v1 += __shfl_xor_sync(0xffffu, v1, o);
            }
        }
        unsigned lst = 0u;
        if (lane == 0) {
            g_LGP2[blockIdx.x] = make_float2(v0, v1);
            __threadfence();
            if (atomicAdd(&g_c1[grp], 1u) == 15u) {
                atomicExch(&g_c1[grp], 0u);
                if (atomicAdd(&g_c0, 1u) == 7u) { atomicExch(&g_c0, 0u); lst = 1u; }
            }
        }
        lst = __shfl_sync(0xffffffffu, lst, 0);
        if (lst) { __threadfence(); if (lane < 8) stflag(&g_flagL[lane * 32], 1u); }
        else if (lane == 0) { while (ldflag(&g_flagL[grp * 32]) < 1u) __nanosleep(20); }
        __syncwarp();
        __threadfence();
        float2 p0 = __ldcg(&g_LGP2[j0]),     p1 = __ldcg(&g_LGP2[j0 + 1]);
        float2 p2 = __ldcg(&g_LGP2[j0 + 2]), p3 = __ldcg(&g_LGP2[j0 + 3]);
        double T0 = (double)p0.x + (double)p1.x + (double)p2.x + (double)p3.x;
        double T1 = (double)p0.y + (double)p1.y + (double)p2.y + (double)p3.y;
        T0 = dsum32(T0); T1 = dsum32(T1);
        double cnt = (double)NCURVE * KN, mu = T0 / cnt;
        if (lane == 0) {
            s_st[4] = (float)mu;
            s_st[5] = (float)(1.0 / sqrt(T1 / cnt - mu * mu + (double)EPSBN));
        }
    }
    __syncthreads();
    if (!isH) {
        float val = (r - s_st[4]) * s_st[5] * ga + ba;
        float bv = val; int bk = lane;
        #pragma unroll
        for (int o = 16; o; o >>= 1) {
            float ov = __shfl_xor_sync(0xffffffffu, bv, o);
            int   ok = __shfl_xor_sync(0xffffffffu, bk, o);
            if (ov > bv || (ov == bv && ok < bk)) { bv = ov; bk = ok; }
        }
        int sel = __shfl_sync(0xffffffffu, nbr, bk);
        rc1 = __ldg(XWf + (size_t)sel * CH + c1);
        rc2 = __ldg(XWf + (size_t)sel * CH + c2);
        s_cur[warp][c1] = rc1; s_cur[warp][c2] = rc2;
        out[((size_t)(b * CH + c1) * CN + ci) * CLEN + 0] = rc1;
        out[((size_t)(b * CH + c2) * CN + ci) * CLEN + 0] = rc2;
        fcur = sel;
    }
    __syncwarp();

    // ---------- steps 1..31 ----------
    const int sh = lane >> 4, sc = lane & 15;
    for (int s = 1; s < CLEN; ++s) {
        float pn1 = 0.f, pn2 = 0.f, anorm = 0.f;
        if (!isH) {
            // A: prefetch neighbors + stage rows (depends only on fcur)
            nbr = __ldg(idxp + (size_t)fcur * KN + lane) + bOff;
            gatt = __ldg(g_GATT + nbr);
            #pragma unroll
            for (int t = 0; t < 16; ++t) {
                int rr = 2 * t + sh;
                int rn = __shfl_sync(0xffffffffu, nbr, rr);
                unsigned dst = sbase + ((unsigned)(warp * 512 + rr * 16 + (sc ^ (rr & 15))) << 4);
                cpasync16(dst, (const void*)(g_XW4 + (size_t)rn * 16 + sc));
            }
            asm volatile("cp.async.commit_group;");

            // B: momentum partials
            float mm0 = wsum(mw0a * rc1 + mw0b * rc2 + mw0c * rp1 + mw0d * rp2);
            float mm1 = wsum(mw1a * rc1 + mw1b * rc2 + mw1c * rp1 + mw1d * rp2);
            if (lane == 0) {
                g_MMBUF[b * 512 + ci]       = mm0;
                g_MMBUF[b * 512 + 256 + ci] = mm1;
                s_red[warp][0] = mm0; s_red[warp][1] = mm0 * mm0;
                s_red[warp][2] = mm1; s_red[warp][3] = mm1 * mm1;
            }
        }
        __syncthreads();                     // B1: partials ready
        if (isH) {
            float v0 = 0.f, v1 = 0.f, v2 = 0.f, v3 = 0.f;
            if (lane < WBLK) {
                v0 = s_red[lane][0]; v1 = s_red[lane][1];
                v2 = s_red[lane][2]; v3 = s_red[lane][3];
                #pragma unroll
                for (int o = 8; o; o >>= 1) {
                    v0 += __shfl_xor_sync(0xffffu, v0, o);
                    v1 += __shfl_xor_sync(0xffffu, v1, o);
                    v2 += __shfl_xor_sync(0xffffu, v2, o);
                    v3 += __shfl_xor_sync(0xffffu, v3, o);
                }
            }
            unsigned lst = 0u;
            if (lane == 0) {
                g_MMP4[blockIdx.x] = make_float4(v0, v1, v2, v3);
                __threadfence();
                if (atomicAdd(&g_c1[grp], 1u) == 15u) {
                    atomicExch(&g_c1[grp], 0u);
                    if (atomicAdd(&g_c0, 1u) == 7u) { atomicExch(&g_c0, 0u); lst = 1u; }
                }
            }
            lst = __shfl_sync(0xffffffffu, lst, 0);
            if (lst) { __threadfence(); if (lane < 8) stflag(&g_flagM[lane * 32], (unsigned)s); }
            else if (lane == 0) { while (ldflag(&g_flagM[grp * 32]) < (unsigned)s) __nanosleep(20); }
            __syncwarp();
            __threadfence();
            float4 p0 = __ldcg(&g_MMP4[j0]),     p1 = __ldcg(&g_MMP4[j0 + 1]);
            float4 p2 = __ldcg(&g_MMP4[j0 + 2]), p3 = __ldcg(&g_MMP4[j0 + 3]);
            double M0 = (double)p0.x + (double)p1.x + (double)p2.x + (double)p3.x;
            double M1 = (double)p0.y + (double)p1.y + (double)p2.y + (double)p3.y;
            double M2 = (double)p0.z + (double)p1.z + (double)p2.z + (double)p3.z;
            double M3 = (double)p0.w + (double)p1.w + (double)p2.w + (double)p3.w;
            M0 = dsum32(M0); M1 = dsum32(M1); M2 = dsum32(M2); M3 = dsum32(M3);
            double mu0 = M0 / 2048.0, mu1 = M2 / 2048.0;
            if (lane == 0) {
                s_st[0] = (float)mu0;
                s_st[1] = (float)(1.0 / sqrt(M1 / 2048.0 - mu0 * mu0 + (double)EPSBN));
                s_st[2] = (float)mu1;
                s_st[3] = (float)(1.0 / sqrt(M3 / 2048.0 - mu1 * mu1 + (double)EPSBN));
            }
        }
        __syncthreads();                     // B2: momentum stats ready
        if (!isH) {
            float mme0 = s_st[0], mis0 = s_st[1], mme1 = s_st[2], mis1 = s_st[3];
            // torch .view attention: curve ci reads softmaxed flat positions 2ci, 2ci+1
            float att0, att1;
            #pragma unroll
            for (int j = 0; j < 2; ++j) {
                int f = 2 * ci + j, o = f >> 8, n = f & 255;
                float z0 = (__ldcg(&g_MMBUF[b * 512 + n])       - mme0) * mis0 * gm0 + bm0;
                float z1 = (__ldcg(&g_MMBUF[b * 512 + 256 + n]) - mme1) * mis1 * gm1 + bm1;
                float mx = fmaxf(z0, z1);
                float e0 = expf(z0 - mx), e1 = expf(z1 - mx);
                float sm = ((o == 0) ? e0 : e1) / (e0 + e1);
                if (j == 0) att0 = sm; else att1 = sm;
            }
            pn1 = rc1 * att0 + rp1 * att1;
            pn2 = rc2 * att0 + rp2 * att1;
            float a1v = rc1 - pn1, a2v = rc2 - pn2;
            s_a[warp][c1] = a1v; s_a[warp][c2] = a2v;
            anorm = sqrtf(wsum(a1v * a1v + a2v * a2v));
            float h2 = wsum(pn1 * aw1a + pn2 * aw1b);
            // C: agent logit partials (pre-suppression)
            r = gatt + h2;
            float t0 = wsum(r), t1 = wsum(r * r);
            if (lane == 0) { s_red[warp][0] = t0; s_red[warp][1] = t1; }
        }
        __syncthreads();                     // C1: logit partials ready
        float dotv = 0.f, nrm = 0.f;
        if (isH) {
            float v0 = 0.f, v1 = 0.f;
            if (lane < WBLK) {
                v0 = s_red[lane][0]; v1 = s_red[lane][1];
                #pragma unroll
                for (int o = 8; o; o >>= 1) {
                    v0 += __shfl_xor_sync(0xffffu, v0, o);
                    v1 += __shfl_xor_sync(0xffffu, v1, o);
                }
            }
            unsigned lst = 0u;
            if (lane == 0) {
                g_LGP2[blockIdx.x] = make_float2(v0, v1);
                __threadfence();
                if (atomicAdd(&g_c1[grp], 1u) == 15u) {
                    atomicExch(&g_c1[grp], 0u);
                    if (atomicAdd(&g_c0, 1u) == 7u) { atomicExch(&g_c0, 0u); lst = 1u; }
                }
            }
            lst = __shfl_sync(0xffffffffu, lst, 0);
            unsigned want = (unsigned)(s + 1);
            if (lst) { __threadfence(); if (lane < 8) stflag(&g_flagL[lane * 32], want); }
            else if (lane == 0) { while (ldflag(&g_flagL[grp * 32]) < want) __nanosleep(20); }
            __syncwarp();
            __threadfence();
            float2 p0 = __ldcg(&g_LGP2[j0]),     p1 = __ldcg(&g_LGP2[j0 + 1]);
            float2 p2 = __ldcg(&g_LGP2[j0 + 2]), p3 = __ldcg(&g_LGP2[j0 + 3]);
            double T0 = (double)p0.x + (double)p1.x + (double)p2.x + (double)p3.x;
            double T1 = (double)p0.y + (double)p1.y + (double)p2.y + (double)p3.y;
            T0 = dsum32(T0); T1 = dsum32(T1);
            double cnt = (double)NCURVE * KN, mu = T0 / cnt;
            if (lane == 0) {
                s_st[4] = (float)mu;
                s_st[5] = (float)(1.0 / sqrt(T1 / cnt - mu * mu + (double)EPSBN));
            }
        } else {
            // D: crossover from staged smem (overlaps handler's barrier wait)
            asm volatile("cp.async.wait_group 0;");
            __syncwarp();
            const int rbase = warp * 512 + lane * 16;
            const int jm = lane & 15;
            #pragma unroll
            for (int t = 0; t < 16; ++t) {
                float4 v = s_rows[rbase + (t ^ jm)];
                int cb = 4 * t; float df;
                df = v.x - s_cur[warp][cb];   dotv = fmaf(s_a[warp][cb],   df, dotv); nrm = fmaf(df, df, nrm);
                df = v.y - s_cur[warp][cb+1]; dotv = fmaf(s_a[warp][cb+1], df, dotv); nrm = fmaf(df, df, nrm);
                df = v.z - s_cur[warp][cb+2]; dotv = fmaf(s_a[warp][cb+2], df, dotv); nrm = fmaf(df, df, nrm);
                df = v.w - s_cur[warp][cb+3]; dotv = fmaf(s_a[warp][cb+3], df, dotv); nrm = fmaf(df, df, nrm);
            }
        }
        __syncthreads();                     // C2: logit stats ready
        if (!isH) {
            float lm = s_st[4], li = s_st[5];
            float val = (r - lm) * li * ga + ba;
            float div = fmaxf(anorm * sqrtf(nrm), 1e-8f);
            float dd = 1.f + dotv / div;
            dd = fminf(fmaxf(dd, 0.f), 1.f);
            val *= dd;

            float bv = val; int bk = lane;
            #pragma unroll
            for (int o = 16; o; o >>= 1) {
                float ov = __shfl_xor_sync(0xffffffffu, bv, o);
                int   ok = __shfl_xor_sync(0xffffffffu, bk, o);
                if (ov > bv || (ov == bv && ok < bk)) { bv = ov; bk = ok; }
            }
            int sel = __shfl_sync(0xffffffffu, nbr, bk);
            rp1 = pn1; rp2 = pn2;
            // cur row from staged smem (bit-verified in R8)
            {
                const int rb2 = warp * 512 + bk * 16, km = bk & 15;
                float4 v1 = s_rows[rb2 + ((lane >> 2) ^ km)];
                float4 v2 = s_rows[rb2 + (((lane >> 2) + 8) ^ km)];
                int cc = lane & 3;
                rc1 = (cc == 0) ? v1.x : (cc == 1) ? v1.y : (cc == 2) ? v1.z : v1.w;
                rc2 = (cc == 0) ? v2.x : (cc == 1) ? v2.y : (cc == 2) ? v2.z : v2.w;
            }
            s_cur[warp][c1] = rc1; s_cur[warp][c2] = rc2;
            out[((size_t)(b * CH + c1) * CN + ci) * CLEN + s] = rc1;
            out[((size_t)(b * CH + c2) * CN + ci) * CLEN + s] = rc2;
            fcur = sel;
        }
        __syncwarp();
    }
}

extern "C" void kernel_launch(void* const* d_in, const int* in_sizes, int n_in,
                              void* d_out, int out_size) {
    const float* x       = (const float*)d_in[0];
    const int*   idx     = (const int*)d_in[2];
    const float* att_w   = (const float*)d_in[3];
    const float* agent_w = (const float*)d_in[4];
    const float* agent_g = (const float*)d_in[5];
    const float* agent_b = (const float*)d_in[6];
    const float* mom_w   = (const float*)d_in[7];
    const float* mom_g   = (const float*)d_in[8];
    const float* mom_b   = (const float*)d_in[9];
    float* out = (float*)d_out;
    (void)in_sizes; (void)n_in; (void)out_size;

    cudaFuncSetAttribute(k_walk, cudaFuncAttributeMaxDynamicSharedMemorySize, DSMEM);

    k_prep<<<NNODE / 128, 128>>>(x, att_w, agent_w);
    k_topk<<<BNS, 1024>>>();
    k_walk<<<NBLK, TPB, DSMEM>>>(idx, agent_w, agent_g, agent_b, mom_w, mom_g, mom_b, out);
}